// round 8
// baseline (speedup 1.0000x reference)
#include <cuda_runtime.h>
#include <cstdint>

#define D 64
#define NUM_REL 32
#define MAXB 131072
#define GROUP 128
#define MAX_GROUPS (MAXB / GROUP + NUM_REL)   // 1056
#define THREADS 256

// dynamic smem layout
#define SM_IDX   0                    // 128 ints (512 B)
#define SM_RD    1024                 // Rdup: 64 k * 512 B = 32 KB
#define SM_E1T   (SM_RD + 32768)      // E1t[k][m]: 64*128*4 = 32 KB (reused as partials)
#define SMEM_TOTAL (SM_E1T + 32768)   // 66560 B

// Scratch (static device globals — zero-initialized at module load)
__device__ int g_counts[NUM_REL];
__device__ int g_n[NUM_REL];
__device__ int g_table[MAX_GROUPS];
__device__ int g_idx[NUM_REL * MAXB];
__device__ int g_done;

// ---------------------------------------------------------------------------
// f32x2 packed-math helpers (sm_103a FFMA2 — PTX-only)
// ---------------------------------------------------------------------------
__device__ __forceinline__ unsigned long long fma2(unsigned long long a,
                                                   unsigned long long b,
                                                   unsigned long long c) {
    unsigned long long d;
    asm("fma.rn.f32x2 %0, %1, %2, %3;" : "=l"(d) : "l"(a), "l"(b), "l"(c));
    return d;
}
__device__ __forceinline__ void unpack2(unsigned long long v, float& x, float& y) {
    unsigned int lo, hi;
    asm("mov.b64 {%0, %1}, %2;" : "=r"(lo), "=r"(hi) : "l"(v));
    x = __uint_as_float(lo);
    y = __uint_as_float(hi);
}

// ---------------------------------------------------------------------------
// Kernel 1: bucket + fused plan (proven in rounds 6)
// ---------------------------------------------------------------------------
__global__ void bucket_kernel(const int* __restrict__ rels, int B) {
    __shared__ int s_count[NUM_REL];
    __shared__ int s_base[NUM_REL];
    __shared__ int s_last;
    const int t    = threadIdx.x;
    const int lane = t & 31;
    if (t < NUM_REL) s_count[t] = 0;
    __syncthreads();

    const int i = blockIdx.x * blockDim.x + t;
    int r = 0, lp = 0;
    const bool valid = (i < B);
    if (valid) r = rels[i];

    {
        unsigned am = __ballot_sync(0xffffffffu, valid);
        if (valid) {
            unsigned mask   = __match_any_sync(am, r);
            int      leader = __ffs(mask) - 1;
            int      rank   = __popc(mask & ((1u << lane) - 1));
            int      base   = 0;
            if (lane == leader) base = atomicAdd(&s_count[r], __popc(mask));
            base = __shfl_sync(am, base, leader);
            lp = base + rank;
        }
    }
    __syncthreads();
    if (t < NUM_REL) s_base[t] = atomicAdd(&g_counts[t], s_count[t]);
    __syncthreads();
    if (valid) g_idx[r * MAXB + s_base[r] + lp] = i;

    __threadfence();
    __syncthreads();
    if (t == 0) {
        int ticket = atomicAdd(&g_done, 1);
        s_last = (ticket == (int)gridDim.x - 1);
    }
    __syncthreads();
    if (s_last && t < 32) {
        int n = atomicAdd(&g_counts[t], 0);
        g_n[t] = n;
        g_counts[t] = 0;
        int ng = (n + GROUP - 1) / GROUP;
        int s = ng;
        #pragma unroll
        for (int o = 1; o < 32; o <<= 1) {
            int v = __shfl_up_sync(0xffffffffu, s, o);
            if (t >= o) s += v;
        }
        int start = s - ng;
        int total = __shfl_sync(0xffffffffu, s, 31);
        for (int g = 0; g < ng; g++) g_table[start + g] = t | (g << 8);
        for (int j = total + t; j < MAX_GROUPS; j += 32) g_table[j] = -1;
        if (t == 0) g_done = 0;
    }
}

// ---------------------------------------------------------------------------
// Kernel 2: score. Block = 128 samples of one relation, 256 threads.
// Thread (mg = t>>3, ng = t&7) computes samples [mg*4, mg*4+4) x cols
// [ng*8, ng*8+8). Accumulators are f32x2 packed over SAMPLE PAIRS:
//   a (LDS.64 of adjacent E1t values)  -> no packing MOVs
//   b from Rdup (values pre-duplicated) -> no packing MOVs
// Rdup layout: [k][j][ng] 16B entries (v0,v0,v1,v1), v = R[k][ng*8+2j(+1)],
// so a warp's 8 ng-lanes hit 8 consecutive 16B lines -> conflict-free.
// ---------------------------------------------------------------------------
__global__ void __launch_bounds__(THREADS, 3)
score_kernel(const float* __restrict__ e1g,
             const float* __restrict__ e2g,
             const float* __restrict__ relw,
             float* __restrict__ out)
{
    extern __shared__ __align__(1024) char smem[];
    int*   s_idx = reinterpret_cast<int*>(smem + SM_IDX);
    char*  sRd   = smem + SM_RD;
    float* E1t   = reinterpret_cast<float*>(smem + SM_E1T);

    const int item = g_table[blockIdx.x];
    if (item < 0) return;
    const int r    = item & 255;
    const int grp  = item >> 8;
    const int cnt0 = g_n[r] - grp * GROUP;
    const int cnt  = cnt0 < GROUP ? cnt0 : GROUP;
    const int* __restrict__ idx = g_idx + r * MAXB + grp * GROUP;

    const int t = threadIdx.x;
    if (t < GROUP) s_idx[t] = idx[t < cnt ? t : cnt - 1];
    __syncthreads();   // s_idx visible for staging

    // ---- stage Rdup: entry e -> k = e>>5, j = (e>>3)&3, ng = e&7 ----
    {
        const float* Rr = relw + r * (D * D);
        #pragma unroll
        for (int it = 0; it < 8; it++) {
            int e  = t + it * THREADS;          // 0..2047
            int k  = e >> 5;
            int j  = (e >> 3) & 3;
            int ng = e & 7;
            float2 v = *reinterpret_cast<const float2*>(Rr + k * D + ng * 8 + 2 * j);
            uint32_t b0 = __float_as_uint(v.x), b1 = __float_as_uint(v.y);
            *reinterpret_cast<uint4*>(sRd + k * 512 + j * 128 + ng * 16) =
                make_uint4(b0, b0, b1, b1);
        }
    }
    // ---- stage E1t[k][m]: sample = t&127, k-half = t>>7 ----
    {
        const int sm = t & 127;
        const int hf = t >> 7;
        const int b  = s_idx[sm];
        const float4* p1 = reinterpret_cast<const float4*>(e1g + b * D) + hf * 8;
        #pragma unroll
        for (int k4 = 0; k4 < 8; k4++) {
            float4 v = p1[k4];
            const int k = hf * 32 + k4 * 4;
            E1t[(k + 0) * GROUP + sm] = v.x;
            E1t[(k + 1) * GROUP + sm] = v.y;
            E1t[(k + 2) * GROUP + sm] = v.z;
            E1t[(k + 3) * GROUP + sm] = v.w;
        }
    }
    __syncthreads();

    const int mg = t >> 3;         // 0..31 : samples mg*4 .. mg*4+3
    const int ng = t & 7;          // 0..7  : cols ng*8 .. ng*8+7
    const int m0 = mg * 4;

    // acc[p][c] = (T[m0+2p][n0+c], T[m0+2p+1][n0+c])
    unsigned long long acc[2][8];
    #pragma unroll
    for (int p = 0; p < 2; p++)
        #pragma unroll
        for (int c = 0; c < 8; c++) acc[p][c] = 0ull;

    const char*  brow = sRd + ng * 16;
    const float* arow = E1t + m0;

    #pragma unroll 4
    for (int k = 0; k < D; k++) {
        unsigned long long a0 =
            *reinterpret_cast<const unsigned long long*>(arow + k * GROUP);
        unsigned long long a1 =
            *reinterpret_cast<const unsigned long long*>(arow + k * GROUP + 2);
        const char* bk = brow + k * 512;
        #pragma unroll
        for (int j = 0; j < 4; j++) {
            ulonglong2 bq = *reinterpret_cast<const ulonglong2*>(bk + j * 128);
            acc[0][2 * j]     = fma2(a0, bq.x, acc[0][2 * j]);
            acc[0][2 * j + 1] = fma2(a0, bq.y, acc[0][2 * j + 1]);
            acc[1][2 * j]     = fma2(a1, bq.x, acc[1][2 * j]);
            acc[1][2 * j + 1] = fma2(a1, bq.y, acc[1][2 * j + 1]);
        }
    }
    __syncthreads();   // done reading E1t/Rdup — reuse E1t as partials

    // ---- epilogue: partial[m] = sum_c T[m][n0+c] * e2[m][n0+c] ----
    float* s_part = E1t;   // [8 ng][128 m]
    #pragma unroll
    for (int p = 0; p < 2; p++) {
        const int ma = m0 + 2 * p;      // sample of component 0
        const int mb = ma + 1;          // sample of component 1
        const int ba = s_idx[ma];
        const int bb = s_idx[mb];
        const float4* ua = reinterpret_cast<const float4*>(e2g + ba * D + ng * 8);
        const float4* ub = reinterpret_cast<const float4*>(e2g + bb * D + ng * 8);
        float4 ua0 = ua[0], ua1 = ua[1];
        float4 ub0 = ub[0], ub1 = ub[1];
        float sa = 0.f, sb = 0.f;
        float x, y;
        unpack2(acc[p][0], x, y); sa += x * ua0.x; sb += y * ub0.x;
        unpack2(acc[p][1], x, y); sa += x * ua0.y; sb += y * ub0.y;
        unpack2(acc[p][2], x, y); sa += x * ua0.z; sb += y * ub0.z;
        unpack2(acc[p][3], x, y); sa += x * ua0.w; sb += y * ub0.w;
        unpack2(acc[p][4], x, y); sa += x * ua1.x; sb += y * ub1.x;
        unpack2(acc[p][5], x, y); sa += x * ua1.y; sb += y * ub1.y;
        unpack2(acc[p][6], x, y); sa += x * ua1.z; sb += y * ub1.z;
        unpack2(acc[p][7], x, y); sa += x * ua1.w; sb += y * ub1.w;
        s_part[ng * GROUP + ma] = sa;
        s_part[ng * GROUP + mb] = sb;
    }
    __syncthreads();

    // deterministic fixed-order reduction + store
    if (t < cnt) {
        float s = 0.0f;
        #pragma unroll
        for (int j = 0; j < 8; j++) s += s_part[j * GROUP + t];
        out[s_idx[t]] = s;
    }
}

// ---------------------------------------------------------------------------
// kernel_launch
// inputs: embeds1 [B*64] f32, embeds2 [B*64] f32, rels [B] i32,
//         rel_embeds [32*4096] f32 ; output [B] f32
// ---------------------------------------------------------------------------
extern "C" void kernel_launch(void* const* d_in, const int* in_sizes, int n_in,
                              void* d_out, int out_size) {
    const float* e1   = (const float*)d_in[0];
    const float* e2   = (const float*)d_in[1];
    const int*   rels = (const int*)d_in[2];
    const float* relw = (const float*)d_in[3];
    float* out = (float*)d_out;

    const int B = in_sizes[2];

    cudaFuncSetAttribute(score_kernel,
                         cudaFuncAttributeMaxDynamicSharedMemorySize, SMEM_TOTAL);

    bucket_kernel<<<(B + 255) / 256, 256>>>(rels, B);
    score_kernel<<<MAX_GROUPS, THREADS, SMEM_TOTAL>>>(e1, e2, relw, out);
}

// round 9
// speedup vs baseline: 1.7147x; 1.7147x over previous
#include <cuda_runtime.h>
#include <cuda_bf16.h>
#include <cstdint>

#define D 64
#define NUM_REL 32
#define MAXB 131072
#define GROUP 128
#define MAX_GROUPS (MAXB / GROUP + NUM_REL)   // 1056
#define THREADS 128

// dynamic smem layout (bytes)
#define SM_IDX  0                      // 128 ints
#define SM_AHI  1024                   // 128 rows x 128 B (bf16 hi)   16 KB
#define SM_ALO  (SM_AHI + 16384)       // 16 KB   (A region doubles as Rtmp)
#define SM_BHI  (SM_ALO + 16384)       // 64 rows x 128 B (bf16 hi)     8 KB
#define SM_BLO  (SM_BHI + 8192)        // 8 KB
#define SMEM_TOTAL (SM_BLO + 8192)     // 50176 B

// Scratch (static device globals — zero-initialized at module load)
__device__ int g_counts[NUM_REL];
__device__ int g_n[NUM_REL];
__device__ int g_table[MAX_GROUPS];
__device__ int g_idx[NUM_REL * MAXB];
__device__ int g_done;

// ---------------------------------------------------------------------------
// helpers
// ---------------------------------------------------------------------------
__device__ __forceinline__ uint32_t smem_u32(const void* p) {
    uint32_t a;
    asm("{ .reg .u64 t; cvta.to.shared.u64 t, %1; cvt.u32.u64 %0, t; }"
        : "=r"(a) : "l"(p));
    return a;
}
// fp32 pair -> bf16x2 (hi) + bf16x2 (lo residual); low half = first element
__device__ __forceinline__ void split2(float x0, float x1, uint32_t& hi, uint32_t& lo) {
    __nv_bfloat162 hv = __floats2bfloat162_rn(x0, x1);
    __nv_bfloat162 lv = __floats2bfloat162_rn(x0 - __bfloat162float(hv.x),
                                              x1 - __bfloat162float(hv.y));
    hi = *reinterpret_cast<uint32_t*>(&hv);
    lo = *reinterpret_cast<uint32_t*>(&lv);
}
__device__ __forceinline__ void ldsm_x4(uint32_t addr, uint32_t& r0, uint32_t& r1,
                                        uint32_t& r2, uint32_t& r3) {
    asm volatile("ldmatrix.sync.aligned.m8n8.x4.shared.b16 {%0,%1,%2,%3}, [%4];"
                 : "=r"(r0), "=r"(r1), "=r"(r2), "=r"(r3) : "r"(addr));
}
// D(fp32) += A(bf16 m16k16) * B(bf16 k16n8)
__device__ __forceinline__ void mma_bf16(float* c, const uint32_t* a,
                                         uint32_t b0, uint32_t b1) {
    asm volatile(
        "mma.sync.aligned.m16n8k16.row.col.f32.bf16.bf16.f32 "
        "{%0,%1,%2,%3}, {%4,%5,%6,%7}, {%8,%9}, {%0,%1,%2,%3};"
        : "+f"(c[0]), "+f"(c[1]), "+f"(c[2]), "+f"(c[3])
        : "r"(a[0]), "r"(a[1]), "r"(a[2]), "r"(a[3]), "r"(b0), "r"(b1));
}

// ---------------------------------------------------------------------------
// Kernel 1: bucket + fused plan (proven)
// ---------------------------------------------------------------------------
__global__ void bucket_kernel(const int* __restrict__ rels, int B) {
    __shared__ int s_count[NUM_REL];
    __shared__ int s_base[NUM_REL];
    __shared__ int s_last;
    const int t    = threadIdx.x;
    const int lane = t & 31;
    if (t < NUM_REL) s_count[t] = 0;
    __syncthreads();

    const int i = blockIdx.x * blockDim.x + t;
    int r = 0, lp = 0;
    const bool valid = (i < B);
    if (valid) r = rels[i];

    {
        unsigned am = __ballot_sync(0xffffffffu, valid);
        if (valid) {
            unsigned mask   = __match_any_sync(am, r);
            int      leader = __ffs(mask) - 1;
            int      rank   = __popc(mask & ((1u << lane) - 1));
            int      base   = 0;
            if (lane == leader) base = atomicAdd(&s_count[r], __popc(mask));
            base = __shfl_sync(am, base, leader);
            lp = base + rank;
        }
    }
    __syncthreads();
    if (t < NUM_REL) s_base[t] = atomicAdd(&g_counts[t], s_count[t]);
    __syncthreads();
    if (valid) g_idx[r * MAXB + s_base[r] + lp] = i;

    __threadfence();
    __syncthreads();
    if (t == 0) {
        int ticket = atomicAdd(&g_done, 1);
        s_last = (ticket == (int)gridDim.x - 1);
    }
    __syncthreads();
    if (s_last && t < 32) {
        int n = atomicAdd(&g_counts[t], 0);
        g_n[t] = n;
        g_counts[t] = 0;
        int ng = (n + GROUP - 1) / GROUP;
        int s = ng;
        #pragma unroll
        for (int o = 1; o < 32; o <<= 1) {
            int v = __shfl_up_sync(0xffffffffu, s, o);
            if (t >= o) s += v;
        }
        int start = s - ng;
        int total = __shfl_sync(0xffffffffu, s, 31);
        for (int g = 0; g < ng; g++) g_table[start + g] = t | (g << 8);
        for (int j = total + t; j < MAX_GROUPS; j += 32) g_table[j] = -1;
        if (t == 0) g_done = 0;
    }
}

// ---------------------------------------------------------------------------
// Kernel 2: score via mma.sync bf16 2-term split.
// Block = 128 samples of one relation, 4 warps; warp w owns m-rows [32w,32w+32).
// T(fp32) = Ahi@Bhi + Ahi@Blo + Alo@Bhi; epilogue dots fragments with e2.
// smem rows are 128 B with chunk swizzle: chunk' = chunk ^ (row & 7).
// ---------------------------------------------------------------------------
__global__ void __launch_bounds__(THREADS, 3)
score_kernel(const float* __restrict__ e1g,
             const float* __restrict__ e2g,
             const float* __restrict__ relw,
             float* __restrict__ out)
{
    extern __shared__ __align__(1024) char smem[];
    const uint32_t sb = smem_u32(smem);
    int* s_idx = reinterpret_cast<int*>(smem + SM_IDX);

    const int item = g_table[blockIdx.x];
    if (item < 0) return;
    const int r    = item & 255;
    const int grp  = item >> 8;
    const int cnt0 = g_n[r] - grp * GROUP;
    const int cnt  = cnt0 < GROUP ? cnt0 : GROUP;
    const int* __restrict__ idx = g_idx + r * MAXB + grp * GROUP;

    const int t = threadIdx.x;
    s_idx[t] = idx[t < cnt ? t : cnt - 1];

    // ---- stage R (coalesced) into A region as fp32 scratch ----
    float* Rtmp = reinterpret_cast<float*>(smem + SM_AHI);
    {
        const float4* src = reinterpret_cast<const float4*>(relw + r * (D * D));
        float4* dst = reinterpret_cast<float4*>(Rtmp);
        #pragma unroll
        for (int i = t; i < (D * D) / 4; i += THREADS) dst[i] = src[i];
    }
    __syncthreads();

    // ---- B = R^T split: thread (n = t&63, half h = t>>6 -> k in [32h,32h+32) )
    {
        const int n = t & 63, h = t >> 6;
        #pragma unroll
        for (int j = 0; j < 4; j++) {              // chunk j of this half
            const int c = h * 4 + j;               // chunk index 0..7 (8 bf16 each)
            uint32_t hi[4], lo[4];
            #pragma unroll
            for (int q = 0; q < 4; q++) {          // 4 bf16x2 pairs per chunk
                const int k = c * 8 + q * 2;
                split2(Rtmp[k * D + n], Rtmp[(k + 1) * D + n], hi[q], lo[q]);
            }
            const uint32_t off = (uint32_t)(n * 128 + ((c ^ (n & 7)) << 4));
            *reinterpret_cast<uint4*>(smem + SM_BHI + off) =
                make_uint4(hi[0], hi[1], hi[2], hi[3]);
            *reinterpret_cast<uint4*>(smem + SM_BLO + off) =
                make_uint4(lo[0], lo[1], lo[2], lo[3]);
        }
    }
    __syncthreads();   // B staged; A region free to overwrite

    // ---- A = gathered e1 rows split: thread t -> sample row m = t ----
    {
        const int m = t;
        const int b = s_idx[m];
        const float4* p1 = reinterpret_cast<const float4*>(e1g + b * D);
        #pragma unroll
        for (int c = 0; c < 8; c++) {              // chunk c: k = 8c..8c+7
            float4 f0 = p1[2 * c];
            float4 f1 = p1[2 * c + 1];
            uint32_t h0, l0, h1, l1, h2, l2, h3, l3;
            split2(f0.x, f0.y, h0, l0);
            split2(f0.z, f0.w, h1, l1);
            split2(f1.x, f1.y, h2, l2);
            split2(f1.z, f1.w, h3, l3);
            const uint32_t off = (uint32_t)(m * 128 + ((c ^ (m & 7)) << 4));
            *reinterpret_cast<uint4*>(smem + SM_AHI + off) = make_uint4(h0, h1, h2, h3);
            *reinterpret_cast<uint4*>(smem + SM_ALO + off) = make_uint4(l0, l1, l2, l3);
        }
    }
    __syncthreads();

    // ---- MMA mainloop ----
    const int lane = t & 31;
    const int w    = t >> 5;

    float acc[2][8][4];
    #pragma unroll
    for (int mt = 0; mt < 2; mt++)
        #pragma unroll
        for (int nt = 0; nt < 8; nt++)
            #pragma unroll
            for (int q = 0; q < 4; q++) acc[mt][nt][q] = 0.0f;

    #pragma unroll
    for (int ks = 0; ks < 4; ks++) {
        // A fragments: lanes 0-7 -> (m0-7,klo)=a0, 8-15 -> (m8-15,klo)=a1,
        //              16-23 -> (m0-7,khi)=a2, 24-31 -> (m8-15,khi)=a3
        uint32_t ah[2][4], al[2][4];
        #pragma unroll
        for (int mt = 0; mt < 2; mt++) {
            const int row   = 32 * w + 16 * mt + (lane & 15);
            const int chunk = 2 * ks + (lane >> 4);
            const uint32_t off =
                (uint32_t)(row * 128 + ((chunk ^ (row & 7)) << 4));
            ldsm_x4(sb + SM_AHI + off, ah[mt][0], ah[mt][1], ah[mt][2], ah[mt][3]);
            ldsm_x4(sb + SM_ALO + off, al[mt][0], al[mt][1], al[mt][2], al[mt][3]);
        }
        // B fragments: pair p covers ntiles 2p,2p+1.
        // lanes 0-7:(n0-7,klo) 8-15:(n0-7,khi) 16-23:(n8-15,klo) 24-31:(n8-15,khi)
        uint32_t bh[8][2], bl[8][2];
        #pragma unroll
        for (int p = 0; p < 4; p++) {
            const int n     = 16 * p + ((lane >> 4) << 3) + (lane & 7);
            const int chunk = 2 * ks + ((lane >> 3) & 1);
            const uint32_t off =
                (uint32_t)(n * 128 + ((chunk ^ (n & 7)) << 4));
            ldsm_x4(sb + SM_BHI + off, bh[2 * p][0], bh[2 * p][1],
                                        bh[2 * p + 1][0], bh[2 * p + 1][1]);
            ldsm_x4(sb + SM_BLO + off, bl[2 * p][0], bl[2 * p][1],
                                        bl[2 * p + 1][0], bl[2 * p + 1][1]);
        }
        #pragma unroll
        for (int mt = 0; mt < 2; mt++)
            #pragma unroll
            for (int nt = 0; nt < 8; nt++) {
                mma_bf16(acc[mt][nt], ah[mt], bh[nt][0], bh[nt][1]);
                mma_bf16(acc[mt][nt], ah[mt], bl[nt][0], bl[nt][1]);
                mma_bf16(acc[mt][nt], al[mt], bh[nt][0], bh[nt][1]);
            }
    }

    // ---- epilogue: c-frag lane l: c0,c1 -> row g=l/4, cols 2tg,2tg+1 (+ntile*8)
    //                              c2,c3 -> row g+8. Dot with e2, quad-reduce.
    {
        const int g  = lane >> 2;
        const int tg = lane & 3;
        #pragma unroll
        for (int mt = 0; mt < 2; mt++) {
            #pragma unroll
            for (int v = 0; v < 2; v++) {
                const int m = 32 * w + 16 * mt + g + 8 * v;
                const int b = s_idx[m];
                float p = 0.0f;
                #pragma unroll
                for (int nt = 0; nt < 8; nt++) {
                    const float2 u = *reinterpret_cast<const float2*>(
                        e2g + b * D + nt * 8 + 2 * tg);
                    p += acc[mt][nt][2 * v]     * u.x;
                    p += acc[mt][nt][2 * v + 1] * u.y;
                }
                p += __shfl_xor_sync(0xffffffffu, p, 1);
                p += __shfl_xor_sync(0xffffffffu, p, 2);
                if (tg == 0 && m < cnt) out[b] = p;
            }
        }
    }
}

// ---------------------------------------------------------------------------
// kernel_launch
// inputs: embeds1 [B*64] f32, embeds2 [B*64] f32, rels [B] i32,
//         rel_embeds [32*4096] f32 ; output [B] f32
// ---------------------------------------------------------------------------
extern "C" void kernel_launch(void* const* d_in, const int* in_sizes, int n_in,
                              void* d_out, int out_size) {
    const float* e1   = (const float*)d_in[0];
    const float* e2   = (const float*)d_in[1];
    const int*   rels = (const int*)d_in[2];
    const float* relw = (const float*)d_in[3];
    float* out = (float*)d_out;

    const int B = in_sizes[2];

    cudaFuncSetAttribute(score_kernel,
                         cudaFuncAttributeMaxDynamicSharedMemorySize, SMEM_TOTAL);

    bucket_kernel<<<(B + 255) / 256, 256>>>(rels, B);
    score_kernel<<<MAX_GROUPS, THREADS, SMEM_TOTAL>>>(e1, e2, relw, out);
}

// round 12
// speedup vs baseline: 1.8262x; 1.0650x over previous
#include <cuda_runtime.h>
#include <cuda_bf16.h>
#include <cstdint>

#define D 64
#define NUM_REL 32
#define MAXB 131072
#define GROUP 128
#define MAX_GROUPS (MAXB / GROUP + NUM_REL)   // 1056
#define THREADS 128

// dynamic smem layout (bytes)
#define SM_IDX  0                      // 128 ints
#define SM_AHI  1024                   // 128 rows x 128 B (bf16 hi)   16 KB
#define SM_ALO  (SM_AHI + 16384)       // 16 KB
#define SM_BHI  (SM_ALO + 16384)       // 64 rows x 128 B               8 KB
#define SM_BLO  (SM_BHI + 8192)        // 8 KB  (contiguous after BHI)
#define SMEM_TOTAL (SM_BLO + 8192)     // 50176 B

// Scratch (static device globals — zero-initialized at module load)
__device__ int g_counts[NUM_REL];
__device__ int g_n[NUM_REL];
__device__ int g_table[MAX_GROUPS];
__device__ int g_idx[NUM_REL * MAXB];
__device__ int g_done;
// pre-split, pre-swizzled B smem image per relation:
// 1024 uint4 per relation = [hi: 0..511 | lo: 512..1023]
__device__ uint4 g_Bimg[NUM_REL * 1024];

// ---------------------------------------------------------------------------
// helpers
// ---------------------------------------------------------------------------
__device__ __forceinline__ uint32_t smem_u32(const void* p) {
    uint32_t a;
    asm("{ .reg .u64 t; cvta.to.shared.u64 t, %1; cvt.u32.u64 %0, t; }"
        : "=r"(a) : "l"(p));
    return a;
}
// fp32 pair -> bf16x2 (hi) + bf16x2 (lo residual); low half = first element
__device__ __forceinline__ void split2(float x0, float x1, uint32_t& hi, uint32_t& lo) {
    __nv_bfloat162 hv = __floats2bfloat162_rn(x0, x1);
    __nv_bfloat162 lv = __floats2bfloat162_rn(x0 - __bfloat162float(hv.x),
                                              x1 - __bfloat162float(hv.y));
    hi = *reinterpret_cast<uint32_t*>(&hv);
    lo = *reinterpret_cast<uint32_t*>(&lv);
}
__device__ __forceinline__ void ldsm_x4(uint32_t addr, uint32_t& r0, uint32_t& r1,
                                        uint32_t& r2, uint32_t& r3) {
    asm volatile("ldmatrix.sync.aligned.m8n8.x4.shared.b16 {%0,%1,%2,%3}, [%4];"
                 : "=r"(r0), "=r"(r1), "=r"(r2), "=r"(r3) : "r"(addr));
}
// D(fp32) += A(bf16 m16k16) * B(bf16 k16n8)
__device__ __forceinline__ void mma_bf16(float* c, const uint32_t* a,
                                         uint32_t b0, uint32_t b1) {
    asm volatile(
        "mma.sync.aligned.m16n8k16.row.col.f32.bf16.bf16.f32 "
        "{%0,%1,%2,%3}, {%4,%5,%6,%7}, {%8,%9}, {%0,%1,%2,%3};"
        : "+f"(c[0]), "+f"(c[1]), "+f"(c[2]), "+f"(c[3])
        : "r"(a[0]), "r"(a[1]), "r"(a[2]), "r"(a[3]), "r"(b0), "r"(b1));
}

// ---------------------------------------------------------------------------
// Kernel 1: bucket + prep + fused plan.
// Blocks [0, NB): bucket samples by relation (warp-aggregated atomics).
// Blocks [NB, NB+NUM_REL): build pre-split swizzled B image for one relation.
// Last block to finish (ticket) builds the exact (rel,group) work table.
// ---------------------------------------------------------------------------
__global__ void __launch_bounds__(256)
bucket_kernel(const int* __restrict__ rels, const float* __restrict__ relw, int B) {
    __shared__ int   s_count[NUM_REL];
    __shared__ int   s_base[NUM_REL];
    __shared__ int   s_last;
    __shared__ __align__(16) float Rtmp[D * D];   // prep scratch (16B-aligned)

    const int t     = threadIdx.x;
    const int lane  = t & 31;
    const int nbuck = (int)gridDim.x - NUM_REL;

    if ((int)blockIdx.x >= nbuck) {
        // ---- prep path: relation r ----
        const int r = (int)blockIdx.x - nbuck;
        {
            const float4* src = reinterpret_cast<const float4*>(relw + r * (D * D));
            float4* dst = reinterpret_cast<float4*>(Rtmp);
            #pragma unroll
            for (int i = t; i < (D * D) / 4; i += 256) dst[i] = src[i];
        }
        __syncthreads();
        {
            const int n = t & 63;
            const int cbase = (t >> 6) * 2;          // 2 chunks per thread
            #pragma unroll
            for (int j = 0; j < 2; j++) {
                const int c = cbase + j;             // chunk 0..7 (8 bf16 each)
                uint32_t hi[4], lo[4];
                #pragma unroll
                for (int q = 0; q < 4; q++) {
                    const int k = c * 8 + q * 2;
                    split2(Rtmp[k * D + n], Rtmp[(k + 1) * D + n], hi[q], lo[q]);
                }
                const int e = n * 8 + (c ^ (n & 7));       // 0..511
                g_Bimg[r * 1024 + e]       = make_uint4(hi[0], hi[1], hi[2], hi[3]);
                g_Bimg[r * 1024 + 512 + e] = make_uint4(lo[0], lo[1], lo[2], lo[3]);
            }
        }
    } else {
        // ---- bucket path ----
        if (t < NUM_REL) s_count[t] = 0;
        __syncthreads();

        const int i = blockIdx.x * 256 + t;
        int r = 0, lp = 0;
        const bool valid = (i < B);
        if (valid) r = rels[i];
        {
            unsigned am = __ballot_sync(0xffffffffu, valid);
            if (valid) {
                unsigned mask   = __match_any_sync(am, r);
                int      leader = __ffs(mask) - 1;
                int      rank   = __popc(mask & ((1u << lane) - 1));
                int      base   = 0;
                if (lane == leader) base = atomicAdd(&s_count[r], __popc(mask));
                base = __shfl_sync(am, base, leader);
                lp = base + rank;
            }
        }
        __syncthreads();
        if (t < NUM_REL) s_base[t] = atomicAdd(&g_counts[t], s_count[t]);
        __syncthreads();
        if (valid) g_idx[r * MAXB + s_base[r] + lp] = i;
    }

    // ---- common ticket + plan ----
    __threadfence();
    __syncthreads();
    if (t == 0) {
        int ticket = atomicAdd(&g_done, 1);
        s_last = (ticket == (int)gridDim.x - 1);
    }
    __syncthreads();
    if (s_last && t < 32) {
        int n = atomicAdd(&g_counts[t], 0);
        g_n[t] = n;
        g_counts[t] = 0;
        int ng = (n + GROUP - 1) / GROUP;
        int s = ng;
        #pragma unroll
        for (int o = 1; o < 32; o <<= 1) {
            int v = __shfl_up_sync(0xffffffffu, s, o);
            if (t >= o) s += v;
        }
        int start = s - ng;
        int total = __shfl_sync(0xffffffffu, s, 31);
        for (int g = 0; g < ng; g++) g_table[start + g] = t | (g << 8);
        for (int j = total + t; j < MAX_GROUPS; j += 32) g_table[j] = -1;
        if (t == 0) g_done = 0;
    }
}

// ---------------------------------------------------------------------------
// Kernel 2: score via mma.sync bf16 2-term split (verified round 9 core).
// Block = 128 samples of one relation, 4 warps; warp w owns m-rows [32w,32w+32).
// B staging = coalesced 16 KB copy of the prebuilt image; A gather starts at
// block entry; single __syncthreads before the mainloop.
// ---------------------------------------------------------------------------
__global__ void __launch_bounds__(THREADS, 4)
score_kernel(const float* __restrict__ e1g,
             const float* __restrict__ e2g,
             float* __restrict__ out)
{
    extern __shared__ __align__(1024) char smem[];
    const uint32_t sb = smem_u32(smem);
    int* s_idx = reinterpret_cast<int*>(smem + SM_IDX);

    const int item = g_table[blockIdx.x];
    if (item < 0) return;
    const int r    = item & 255;
    const int grp  = item >> 8;
    const int cnt0 = g_n[r] - grp * GROUP;
    const int cnt  = cnt0 < GROUP ? cnt0 : GROUP;
    const int* __restrict__ idx = g_idx + r * MAXB + grp * GROUP;

    const int t = threadIdx.x;
    const int b = idx[t < cnt ? t : cnt - 1];   // this thread's sample row
    s_idx[t] = b;

    // ---- B staging: copy pre-split swizzled image (1024 uint4 = 16 KB) ----
    {
        const uint4* src = g_Bimg + r * 1024;
        uint4* dst = reinterpret_cast<uint4*>(smem + SM_BHI);
        #pragma unroll
        for (int it = 0; it < 8; it++) dst[t + it * THREADS] = src[t + it * THREADS];
    }

    // ---- A staging: gather own e1 row, split, swizzled stores ----
    {
        const int m = t;
        const float4* p1 = reinterpret_cast<const float4*>(e1g) + b * (D / 4);
        #pragma unroll
        for (int c = 0; c < 8; c++) {              // chunk c: k = 8c..8c+7
            float4 f0 = p1[2 * c];
            float4 f1 = p1[2 * c + 1];
            uint32_t h0, l0, h1, l1, h2, l2, h3, l3;
            split2(f0.x, f0.y, h0, l0);
            split2(f0.z, f0.w, h1, l1);
            split2(f1.x, f1.y, h2, l2);
            split2(f1.z, f1.w, h3, l3);
            const uint32_t off = (uint32_t)(m * 128 + ((c ^ (m & 7)) << 4));
            *reinterpret_cast<uint4*>(smem + SM_AHI + off) = make_uint4(h0, h1, h2, h3);
            *reinterpret_cast<uint4*>(smem + SM_ALO + off) = make_uint4(l0, l1, l2, l3);
        }
    }
    __syncthreads();

    // ---- MMA mainloop (byte-identical logic to round 9) ----
    const int lane = t & 31;
    const int w    = t >> 5;

    float acc[2][8][4];
    #pragma unroll
    for (int mt = 0; mt < 2; mt++)
        #pragma unroll
        for (int nt = 0; nt < 8; nt++)
            #pragma unroll
            for (int q = 0; q < 4; q++) acc[mt][nt][q] = 0.0f;

    #pragma unroll
    for (int ks = 0; ks < 4; ks++) {
        uint32_t ah[2][4], al[2][4];
        #pragma unroll
        for (int mt = 0; mt < 2; mt++) {
            const int row   = 32 * w + 16 * mt + (lane & 15);
            const int chunk = 2 * ks + (lane >> 4);
            const uint32_t off =
                (uint32_t)(row * 128 + ((chunk ^ (row & 7)) << 4));
            ldsm_x4(sb + SM_AHI + off, ah[mt][0], ah[mt][1], ah[mt][2], ah[mt][3]);
            ldsm_x4(sb + SM_ALO + off, al[mt][0], al[mt][1], al[mt][2], al[mt][3]);
        }
        uint32_t bh[8][2], bl[8][2];
        #pragma unroll
        for (int p = 0; p < 4; p++) {
            const int n     = 16 * p + ((lane >> 4) << 3) + (lane & 7);
            const int chunk = 2 * ks + ((lane >> 3) & 1);
            const uint32_t off =
                (uint32_t)(n * 128 + ((chunk ^ (n & 7)) << 4));
            ldsm_x4(sb + SM_BHI + off, bh[2 * p][0], bh[2 * p][1],
                                        bh[2 * p + 1][0], bh[2 * p + 1][1]);
            ldsm_x4(sb + SM_BLO + off, bl[2 * p][0], bl[2 * p][1],
                                        bl[2 * p + 1][0], bl[2 * p + 1][1]);
        }
        #pragma unroll
        for (int mt = 0; mt < 2; mt++)
            #pragma unroll
            for (int nt = 0; nt < 8; nt++) {
                mma_bf16(acc[mt][nt], ah[mt], bh[nt][0], bh[nt][1]);
                mma_bf16(acc[mt][nt], ah[mt], bl[nt][0], bl[nt][1]);
                mma_bf16(acc[mt][nt], al[mt], bh[nt][0], bh[nt][1]);
            }
    }

    // ---- epilogue: dot c-fragments with e2, quad-reduce, store ----
    {
        const int g  = lane >> 2;
        const int tg = lane & 3;
        #pragma unroll
        for (int mt = 0; mt < 2; mt++) {
            #pragma unroll
            for (int v = 0; v < 2; v++) {
                const int m  = 32 * w + 16 * mt + g + 8 * v;
                const int bm = s_idx[m];
                float p = 0.0f;
                #pragma unroll
                for (int nt = 0; nt < 8; nt++) {
                    const float2 u = *reinterpret_cast<const float2*>(
                        e2g + bm * D + nt * 8 + 2 * tg);
                    p += acc[mt][nt][2 * v]     * u.x;
                    p += acc[mt][nt][2 * v + 1] * u.y;
                }
                p += __shfl_xor_sync(0xffffffffu, p, 1);
                p += __shfl_xor_sync(0xffffffffu, p, 2);
                if (tg == 0 && m < cnt) out[bm] = p;
            }
        }
    }
}

// ---------------------------------------------------------------------------
// kernel_launch
// inputs: embeds1 [B*64] f32, embeds2 [B*64] f32, rels [B] i32,
//         rel_embeds [32*4096] f32 ; output [B] f32
// ---------------------------------------------------------------------------
extern "C" void kernel_launch(void* const* d_in, const int* in_sizes, int n_in,
                              void* d_out, int out_size) {
    const float* e1   = (const float*)d_in[0];
    const float* e2   = (const float*)d_in[1];
    const int*   rels = (const int*)d_in[2];
    const float* relw = (const float*)d_in[3];
    float* out = (float*)d_out;

    const int B = in_sizes[2];
    const int NB = (B + 255) / 256;

    cudaFuncSetAttribute(score_kernel,
                         cudaFuncAttributeMaxDynamicSharedMemorySize, SMEM_TOTAL);

    bucket_kernel<<<NB + NUM_REL, 256>>>(rels, relw, B);
    score_kernel<<<MAX_GROUPS, THREADS, SMEM_TOTAL>>>(e1, e2, out);
}